// round 6
// baseline (speedup 1.0000x reference)
#include <cuda_runtime.h>
#include <cuda_fp16.h>
#include <cstdint>

// Problem dims (fixed by dataset)
#define BB 8
#define NN 2048
#define CC 128
#define NQT 16  // NN / 128

// ---------------- scratch (device globals; no allocs allowed) ----------------
__device__ unsigned short g_hn[BB * NN * CC];  // normalized h, fp16, [b][n][c]
__device__ float g_norm[BB * NN];              // per-row L2 norm of h (fp32)

// ---------------- PTX helpers (family-portable: sm_75/80-era) ----------------
__device__ __forceinline__ uint32_t smem_u32(const void* p) {
    uint32_t a;
    asm("{ .reg .u64 t; cvta.to.shared.u64 t, %1; cvt.u32.u64 %0, t; }" : "=r"(a) : "l"(p));
    return a;
}

__device__ __forceinline__ void cp_async16(uint32_t dst, const void* src) {
    asm volatile("cp.async.cg.shared.global [%0], [%1], 16;" :: "r"(dst), "l"(src) : "memory");
}
#define CP_COMMIT() asm volatile("cp.async.commit_group;" ::: "memory")
#define CP_WAIT0()  asm volatile("cp.async.wait_group 0;" ::: "memory")

__device__ __forceinline__ void ldsm_x4(uint32_t* r, uint32_t a) {
    asm volatile("ldmatrix.sync.aligned.m8n8.x4.shared.b16 {%0,%1,%2,%3}, [%4];"
                 : "=r"(r[0]), "=r"(r[1]), "=r"(r[2]), "=r"(r[3]) : "r"(a));
}
__device__ __forceinline__ void ldsm_x4t(uint32_t* r, uint32_t a) {
    asm volatile("ldmatrix.sync.aligned.m8n8.x4.trans.shared.b16 {%0,%1,%2,%3}, [%4];"
                 : "=r"(r[0]), "=r"(r[1]), "=r"(r[2]), "=r"(r[3]) : "r"(a));
}

__device__ __forceinline__ void mma16816(float* d, const uint32_t* a, uint32_t b0, uint32_t b1) {
    asm volatile("mma.sync.aligned.m16n8k16.row.col.f32.f16.f16.f32 "
                 "{%0,%1,%2,%3}, {%4,%5,%6,%7}, {%8,%9}, {%0,%1,%2,%3};"
                 : "+f"(d[0]), "+f"(d[1]), "+f"(d[2]), "+f"(d[3])
                 : "r"(a[0]), "r"(a[1]), "r"(a[2]), "r"(a[3]), "r"(b0), "r"(b1));
}

// pack two f32 -> f16x2 (lo = first arg)
__device__ __forceinline__ uint32_t pack_h2(float lo, float hi) {
    uint32_t d;
    asm("cvt.rn.f16x2.f32 %0, %1, %2;" : "=r"(d) : "f"(hi), "f"(lo));
    return d;
}

// =====================================================================
// Kernel 1: h = x@W^T + b (fp16 MMA) ; norm = ||h|| ; g_hn = h/norm (fp16)
// grid (16,8), 256 threads (8 warps x m16). SMEM: x-tile + W-tile fp16.
// =====================================================================
#define TILE_B 34816                     // 128 rows * 272B (fp16 tile, padded)
#define K1_SMEM (2 * TILE_B + 512)

__global__ __launch_bounds__(256) void k1_linear_norm(const float* __restrict__ x,
                                                      const float* __restrict__ W,
                                                      const float* __restrict__ bias) {
    extern __shared__ char sm1[];
    char* xs = sm1;                 // x tile fp16 (reused as hn stage later)
    char* Ws = sm1 + TILE_B;        // W tile fp16
    float* bs = (float*)(sm1 + 2 * TILE_B);

    const int b = blockIdx.y;
    const int nb0 = blockIdx.x * 128;
    const int tid = threadIdx.x, wid = tid >> 5, lane = tid & 31;

    // stage x and W (fp32 -> fp16), pitch 272B
    {
        const float* xg = x + ((size_t)b * NN + nb0) * CC;
#pragma unroll
        for (int it = 0; it < 16; it++) {
            int i = tid + it * 256;
            int row = i >> 5, c4 = i & 31;
            float4 v = *(const float4*)(xg + (size_t)row * 128 + c4 * 4);
            *(uint2*)(xs + row * 272 + c4 * 8) = make_uint2(pack_h2(v.x, v.y), pack_h2(v.z, v.w));
            float4 w4 = *(const float4*)(W + (size_t)row * 128 + c4 * 4);
            *(uint2*)(Ws + row * 272 + c4 * 8) = make_uint2(pack_h2(w4.x, w4.y), pack_h2(w4.z, w4.w));
        }
        if (tid < 32) *(float4*)&bs[tid * 4] = *(const float4*)(bias + tid * 4);
    }
    __syncthreads();

    // A fragments: warp's m16 rows of x
    uint32_t af[32];
    {
        uint32_t xa = smem_u32(xs) + (uint32_t)((wid * 16 + (lane & 15)) * 272)
                    + ((lane & 16) ? 16 : 0);
#pragma unroll
        for (int kk = 0; kk < 8; kk++) ldsm_x4(af + 4 * kk, xa + kk * 32);
    }

    float Hf[64];
#pragma unroll
    for (int i = 0; i < 64; i++) Hf[i] = 0.0f;

    // B = W rows (o = n dim), non-trans x4 (n16 x k16 per load)
    {
        uint32_t wb = smem_u32(Ws) + (uint32_t)(((lane & 7) + ((lane & 16) ? 8 : 0)) * 272)
                    + ((lane & 8) ? 16 : 0);
#pragma unroll
        for (int jp = 0; jp < 8; jp++) {
#pragma unroll
            for (int kk = 0; kk < 8; kk++) {
                uint32_t bf[4];
                ldsm_x4(bf, wb + (uint32_t)(jp * 16 * 272) + kk * 32);
                mma16816(Hf + (jp * 2) * 4, af + 4 * kk, bf[0], bf[1]);
                mma16816(Hf + (jp * 2 + 1) * 4, af + 4 * kk, bf[2], bf[3]);
            }
        }
    }

    // bias + row sum-of-squares
    float s0 = 0.0f, s1 = 0.0f;
#pragma unroll
    for (int j = 0; j < 16; j++) {
        float2 bv = *(const float2*)&bs[j * 8 + 2 * (lane & 3)];
        Hf[j * 4 + 0] += bv.x; Hf[j * 4 + 1] += bv.y;
        Hf[j * 4 + 2] += bv.x; Hf[j * 4 + 3] += bv.y;
        s0 += Hf[j * 4 + 0] * Hf[j * 4 + 0] + Hf[j * 4 + 1] * Hf[j * 4 + 1];
        s1 += Hf[j * 4 + 2] * Hf[j * 4 + 2] + Hf[j * 4 + 3] * Hf[j * 4 + 3];
    }
    s0 += __shfl_xor_sync(0xFFFFFFFFu, s0, 1); s0 += __shfl_xor_sync(0xFFFFFFFFu, s0, 2);
    s1 += __shfl_xor_sync(0xFFFFFFFFu, s1, 1); s1 += __shfl_xor_sync(0xFFFFFFFFu, s1, 2);
    float n0 = sqrtf(s0), n1 = sqrtf(s1);
    float i0 = 1.0f / fmaxf(n0, 1e-12f), i1 = 1.0f / fmaxf(n1, 1e-12f);
    if ((lane & 3) == 0) {
        g_norm[(size_t)b * NN + nb0 + wid * 16 + (lane >> 2)] = n0;
        g_norm[(size_t)b * NN + nb0 + wid * 16 + (lane >> 2) + 8] = n1;
    }

    __syncthreads();  // done reading xs; reuse as hn staging
    {
        const int r = wid * 16 + (lane >> 2);
#pragma unroll
        for (int j = 0; j < 16; j++) {
            *(uint32_t*)(xs + r * 272 + j * 16 + 4 * (lane & 3)) =
                pack_h2(Hf[j * 4 + 0] * i0, Hf[j * 4 + 1] * i0);
            *(uint32_t*)(xs + (r + 8) * 272 + j * 16 + 4 * (lane & 3)) =
                pack_h2(Hf[j * 4 + 2] * i1, Hf[j * 4 + 3] * i1);
        }
    }
    __syncthreads();
    {
        unsigned short* hng = g_hn + ((size_t)b * NN + nb0) * CC;
#pragma unroll
        for (int it = 0; it < 8; it++) {
            int i = tid + it * 256;
            int row = i >> 4, ch = i & 15;
            *(float4*)(hng + (size_t)row * 128 + ch * 8) = *(const float4*)(xs + row * 272 + ch * 16);
        }
    }
}

// =====================================================================
// Kernel 2: S = hn_p.hn_q^T ; O += (edge*S*norm_q).hn_q ; ReLU
// grid (16,8), 512 threads: 16 warps (mi=wid&7 -> m16, ni=wid>>3 -> n64/k64 split).
// Per-warp partial O reduced across ni-pair once at the end.
// =====================================================================
#define EPITCH 68                        // floats per edge row (272B)
#define OFF_T 0                          // 2 hn tiles (ping-pong)
#define OFF_E (2 * TILE_B)               // 4 edge chunks: (par*2+c)
#define OFF_N (6 * TILE_B)               // 2 x 128 norm floats
#define K2_SMEM (6 * TILE_B + 1024)      // 209920 B

// stage one 128x128 fp16 tile (row-major, 256B rows) -> SMEM pitch 272B  (512 thr)
__device__ __forceinline__ void stage_tile(const unsigned short* src, char* dst, int tid) {
#pragma unroll
    for (int it = 0; it < 4; it++) {
        int i = tid + it * 512;
        int row = i >> 4, ch = i & 15;
        cp_async16(smem_u32(dst + row * 272 + ch * 16), src + (size_t)row * 128 + ch * 8);
    }
}
// stage 128 x 64 floats of edge (gmem row pitch NN) -> SMEM pitch 272B  (512 thr)
__device__ __forceinline__ void stage_edge(const float* src, char* dst, int tid) {
#pragma unroll
    for (int it = 0; it < 4; it++) {
        int i = tid + it * 512;
        int row = i >> 4, ch = i & 15;
        cp_async16(smem_u32(dst + row * 272 + ch * 16), src + (size_t)row * NN + ch * 4);
    }
}

__global__ __launch_bounds__(512, 1) void k2_fused(const float* __restrict__ edge,
                                                   float* __restrict__ out) {
    extern __shared__ char smc[];
    const int b = blockIdx.y, p = blockIdx.x;
    const int tid = threadIdx.x, wid = tid >> 5, lane = tid & 31;
    const int mi = wid & 7, ni = wid >> 3;

    const unsigned short* hnb = g_hn + (size_t)b * NN * CC;
    const float* eb = edge + ((size_t)b * NN + (size_t)p * 128) * NN;
    const float* nb = g_norm + (size_t)b * NN;

    // ---- preload A1 fragments (hn_p, m16 per warp) ----
    stage_tile(hnb + (size_t)p * 128 * CC, smc + OFF_T, tid);
    CP_COMMIT(); CP_WAIT0(); __syncthreads();

    uint32_t a1f[32];
    {
        uint32_t ra = smem_u32(smc + OFF_T) + (uint32_t)((mi * 16 + (lane & 15)) * 272)
                    + ((lane & 16) ? 16 : 0);
#pragma unroll
        for (int kk = 0; kk < 8; kk++) ldsm_x4(a1f + 4 * kk, ra + kk * 32);
    }
    __syncthreads();  // A1 in regs; tile buf 0 reusable

    float Of[64];
#pragma unroll
    for (int i = 0; i < 64; i++) Of[i] = 0.0f;

    // pipeline prologue: q=0 -> parity 0 buffers
    stage_tile(hnb, smc + OFF_T, tid);
    stage_edge(eb, smc + OFF_E, tid);
    stage_edge(eb + 64, smc + OFF_E + TILE_B, tid);
    if (tid < 32) cp_async16(smem_u32(smc + OFF_N) + tid * 16, nb + tid * 4);
    CP_COMMIT();

    const int r0 = mi * 16 + (lane >> 2);
    const int c0 = 2 * (lane & 3);

    for (int q = 0; q < NQT; q++) {
        const int par = q & 1;
        CP_WAIT0();
        __syncthreads();

        // prefetch q+1 into opposite-parity buffers (spans whole q compute)
        if (q < NQT - 1) {
            const int qn = q + 1, pn = par ^ 1;
            stage_tile(hnb + (size_t)qn * 128 * CC, smc + OFF_T + pn * TILE_B, tid);
            stage_edge(eb + (size_t)qn * 128, smc + OFF_E + (pn * 2 + 0) * TILE_B, tid);
            stage_edge(eb + (size_t)qn * 128 + 64, smc + OFF_E + (pn * 2 + 1) * TILE_B, tid);
            if (tid < 32)
                cp_async16(smem_u32(smc + OFF_N) + pn * 512 + tid * 16, nb + qn * 128 + tid * 4);
        }
        CP_COMMIT();

        const uint32_t tb = smem_u32(smc + OFF_T + par * TILE_B);
        const float* ech = (const float*)(smc + OFF_E + (par * 2 + ni) * TILE_B);
        const float* nch = (const float*)(smc + OFF_N + par * 512) + ni * 64;
        const uint32_t b1base = tb + (uint32_t)((ni * 64 + (lane & 7) + ((lane & 16) ? 8 : 0)) * 272)
                              + ((lane & 8) ? 16 : 0);
        const uint32_t b2base = tb + (uint32_t)((ni * 64 + (lane & 15)) * 272)
                              + ((lane & 16) ? 16 : 0);

#pragma unroll
        for (int tt = 0; tt < 4; tt++) {
            // ---- MMA1: S[m16, n16] over k=128 ----
            float S[8];
#pragma unroll
            for (int i = 0; i < 8; i++) S[i] = 0.0f;
            {
                const uint32_t bb1 = b1base + (uint32_t)(tt * 16 * 272);
#pragma unroll
                for (int kk = 0; kk < 8; kk++) {
                    uint32_t bf[4];
                    ldsm_x4(bf, bb1 + kk * 32);
                    mma16816(S + 0, a1f + 4 * kk, bf[0], bf[1]);
                    mma16816(S + 4, a1f + 4 * kk, bf[2], bf[3]);
                }
            }
            // ---- gate: S *= edge * norm_q ----
#pragma unroll
            for (int jj = 0; jj < 2; jj++) {
                const int c = tt * 16 + jj * 8 + c0;
                float2 nv = *(const float2*)&nch[c];
                float2 e0 = *(const float2*)&ech[r0 * EPITCH + c];
                float2 e1 = *(const float2*)&ech[(r0 + 8) * EPITCH + c];
                S[jj * 4 + 0] *= e0.x * nv.x; S[jj * 4 + 1] *= e0.y * nv.y;
                S[jj * 4 + 2] *= e1.x * nv.x; S[jj * 4 + 3] *= e1.y * nv.y;
            }
            // ---- pack A2 (m16 x k16) ----
            uint32_t A2[4];
            A2[0] = pack_h2(S[0], S[1]);
            A2[1] = pack_h2(S[2], S[3]);
            A2[2] = pack_h2(S[4], S[5]);
            A2[3] = pack_h2(S[6], S[7]);
            // ---- MMA2: O[m16, n128] += A2 . hn_q[k16, n128] ----
            {
                const uint32_t bb2 = b2base + (uint32_t)(tt * 16 * 272);
#pragma unroll
                for (int j2p = 0; j2p < 8; j2p++) {
                    uint32_t bf[4];
                    ldsm_x4t(bf, bb2 + j2p * 32);
                    mma16816(Of + (j2p * 2) * 4,     A2, bf[0], bf[1]);
                    mma16816(Of + (j2p * 2 + 1) * 4, A2, bf[2], bf[3]);
                }
            }
        }
    }

    // ---- cross-warp (ni) reduction + ReLU + store ----
    __syncthreads();  // all compute done; edge SMEM reusable
    float* red = (float*)(smc + OFF_E) + mi * (32 * 68) + lane * 68;
    if (ni == 1) {
#pragma unroll
        for (int i4 = 0; i4 < 16; i4++) *(float4*)&red[i4 * 4] = *(const float4*)&Of[i4 * 4];
    }
    __syncthreads();
    if (ni == 0) {
#pragma unroll
        for (int i = 0; i < 64; i++) Of[i] += red[i];
        float* ob = out + ((size_t)b * NN + (size_t)p * 128 + mi * 16) * CC;
        const int rr = lane >> 2;
#pragma unroll
        for (int j2 = 0; j2 < 16; j2++) {
            const int c = j2 * 8 + c0;
            float2 v0, v1;
            v0.x = fmaxf(Of[j2 * 4 + 0], 0.0f);
            v0.y = fmaxf(Of[j2 * 4 + 1], 0.0f);
            v1.x = fmaxf(Of[j2 * 4 + 2], 0.0f);
            v1.y = fmaxf(Of[j2 * 4 + 3], 0.0f);
            *(float2*)&ob[(size_t)rr * CC + c] = v0;
            *(float2*)&ob[(size_t)(rr + 8) * CC + c] = v1;
        }
    }
}

// ---------------- host launch ----------------
extern "C" void kernel_launch(void* const* d_in, const int* in_sizes, int n_in,
                              void* d_out, int out_size) {
    (void)out_size;
    const float *x = nullptr, *edge = nullptr, *W = nullptr, *bias = nullptr;
    for (int i = 0; i < n_in; i++) {
        int sz = in_sizes[i];
        if (sz == BB * NN * CC) x = (const float*)d_in[i];
        else if (sz == BB * NN * NN) edge = (const float*)d_in[i];
        else if (sz == CC * CC) W = (const float*)d_in[i];
        else if (sz == CC) bias = (const float*)d_in[i];
    }
    if (!x) x = (const float*)d_in[0];
    if (!edge) edge = (const float*)d_in[1];
    if (!W) W = (const float*)d_in[2];
    if (!bias) bias = (const float*)d_in[3];
    float* out = (float*)d_out;

    cudaFuncSetAttribute(k1_linear_norm, cudaFuncAttributeMaxDynamicSharedMemorySize, K1_SMEM);
    cudaFuncSetAttribute(k2_fused, cudaFuncAttributeMaxDynamicSharedMemorySize, K2_SMEM);

    k1_linear_norm<<<dim3(16, 8), 256, K1_SMEM>>>(x, W, bias);
    k2_fused<<<dim3(16, 8), 512, K2_SMEM>>>(edge, out);
}

// round 8
// speedup vs baseline: 1.0141x; 1.0141x over previous
#include <cuda_runtime.h>
#include <cuda_fp16.h>
#include <cstdint>

// Problem dims (fixed by dataset)
#define BB 8
#define NN 2048
#define CC 128
#define NQT 16  // NN / 128

// ---------------- scratch (device globals; no allocs allowed) ----------------
__device__ unsigned short g_hn[BB * NN * CC];  // normalized h, fp16, [b][n][c]
__device__ float g_norm[BB * NN];              // per-row L2 norm of h (fp32)

// ---------------- PTX helpers (family-portable: sm_75/80-era) ----------------
__device__ __forceinline__ uint32_t smem_u32(const void* p) {
    uint32_t a;
    asm("{ .reg .u64 t; cvta.to.shared.u64 t, %1; cvt.u32.u64 %0, t; }" : "=r"(a) : "l"(p));
    return a;
}

__device__ __forceinline__ void cp_async16(uint32_t dst, const void* src) {
    asm volatile("cp.async.cg.shared.global [%0], [%1], 16;" :: "r"(dst), "l"(src) : "memory");
}
#define CP_COMMIT() asm volatile("cp.async.commit_group;" ::: "memory")
#define CP_WAIT0()  asm volatile("cp.async.wait_group 0;" ::: "memory")

__device__ __forceinline__ void ldsm_x4(uint32_t* r, uint32_t a) {
    asm volatile("ldmatrix.sync.aligned.m8n8.x4.shared.b16 {%0,%1,%2,%3}, [%4];"
                 : "=r"(r[0]), "=r"(r[1]), "=r"(r[2]), "=r"(r[3]) : "r"(a));
}

// in-register 8x8 b16 transpose: converts MMA1 B-fragments into MMA2 B-fragments
__device__ __forceinline__ uint32_t movm(uint32_t a) {
    uint32_t d;
    asm volatile("movmatrix.sync.aligned.m8n8.trans.b16 %0, %1;" : "=r"(d) : "r"(a));
    return d;
}

__device__ __forceinline__ void mma16816(float* d, const uint32_t* a, uint32_t b0, uint32_t b1) {
    asm volatile("mma.sync.aligned.m16n8k16.row.col.f32.f16.f16.f32 "
                 "{%0,%1,%2,%3}, {%4,%5,%6,%7}, {%8,%9}, {%0,%1,%2,%3};"
                 : "+f"(d[0]), "+f"(d[1]), "+f"(d[2]), "+f"(d[3])
                 : "r"(a[0]), "r"(a[1]), "r"(a[2]), "r"(a[3]), "r"(b0), "r"(b1));
}

// pack two f32 -> f16x2 (lo = first arg)
__device__ __forceinline__ uint32_t pack_h2(float lo, float hi) {
    uint32_t d;
    asm("cvt.rn.f16x2.f32 %0, %1, %2;" : "=r"(d) : "f"(hi), "f"(lo));
    return d;
}

// =====================================================================
// Kernel 1: h = x@W^T + b (fp16 MMA) ; norm = ||h|| ; g_hn = h/norm (fp16)
// grid (16,8), 256 threads (8 warps x m16). SMEM: x-tile + W-tile fp16.
// =====================================================================
#define TILE_B 34816                     // 128 rows * 272B (fp16 tile, padded)
#define K1_SMEM (2 * TILE_B + 512)

__global__ __launch_bounds__(256) void k1_linear_norm(const float* __restrict__ x,
                                                      const float* __restrict__ W,
                                                      const float* __restrict__ bias) {
    extern __shared__ char sm1[];
    char* xs = sm1;                 // x tile fp16 (reused as hn stage later)
    char* Ws = sm1 + TILE_B;        // W tile fp16
    float* bs = (float*)(sm1 + 2 * TILE_B);

    const int b = blockIdx.y;
    const int nb0 = blockIdx.x * 128;
    const int tid = threadIdx.x, wid = tid >> 5, lane = tid & 31;

    // stage x and W (fp32 -> fp16), pitch 272B
    {
        const float* xg = x + ((size_t)b * NN + nb0) * CC;
#pragma unroll
        for (int it = 0; it < 16; it++) {
            int i = tid + it * 256;
            int row = i >> 5, c4 = i & 31;
            float4 v = *(const float4*)(xg + (size_t)row * 128 + c4 * 4);
            *(uint2*)(xs + row * 272 + c4 * 8) = make_uint2(pack_h2(v.x, v.y), pack_h2(v.z, v.w));
            float4 w4 = *(const float4*)(W + (size_t)row * 128 + c4 * 4);
            *(uint2*)(Ws + row * 272 + c4 * 8) = make_uint2(pack_h2(w4.x, w4.y), pack_h2(w4.z, w4.w));
        }
        if (tid < 32) *(float4*)&bs[tid * 4] = *(const float4*)(bias + tid * 4);
    }
    __syncthreads();

    // A fragments: warp's m16 rows of x
    uint32_t af[32];
    {
        uint32_t xa = smem_u32(xs) + (uint32_t)((wid * 16 + (lane & 15)) * 272)
                    + ((lane & 16) ? 16 : 0);
#pragma unroll
        for (int kk = 0; kk < 8; kk++) ldsm_x4(af + 4 * kk, xa + kk * 32);
    }

    float Hf[64];
#pragma unroll
    for (int i = 0; i < 64; i++) Hf[i] = 0.0f;

    // B = W rows (o = n dim), non-trans x4 (n16 x k16 per load)
    {
        uint32_t wb = smem_u32(Ws) + (uint32_t)(((lane & 7) + ((lane & 16) ? 8 : 0)) * 272)
                    + ((lane & 8) ? 16 : 0);
#pragma unroll
        for (int jp = 0; jp < 8; jp++) {
#pragma unroll
            for (int kk = 0; kk < 8; kk++) {
                uint32_t bf[4];
                ldsm_x4(bf, wb + (uint32_t)(jp * 16 * 272) + kk * 32);
                mma16816(Hf + (jp * 2) * 4, af + 4 * kk, bf[0], bf[1]);
                mma16816(Hf + (jp * 2 + 1) * 4, af + 4 * kk, bf[2], bf[3]);
            }
        }
    }

    // bias + row sum-of-squares
    float s0 = 0.0f, s1 = 0.0f;
#pragma unroll
    for (int j = 0; j < 16; j++) {
        float2 bv = *(const float2*)&bs[j * 8 + 2 * (lane & 3)];
        Hf[j * 4 + 0] += bv.x; Hf[j * 4 + 1] += bv.y;
        Hf[j * 4 + 2] += bv.x; Hf[j * 4 + 3] += bv.y;
        s0 += Hf[j * 4 + 0] * Hf[j * 4 + 0] + Hf[j * 4 + 1] * Hf[j * 4 + 1];
        s1 += Hf[j * 4 + 2] * Hf[j * 4 + 2] + Hf[j * 4 + 3] * Hf[j * 4 + 3];
    }
    s0 += __shfl_xor_sync(0xFFFFFFFFu, s0, 1); s0 += __shfl_xor_sync(0xFFFFFFFFu, s0, 2);
    s1 += __shfl_xor_sync(0xFFFFFFFFu, s1, 1); s1 += __shfl_xor_sync(0xFFFFFFFFu, s1, 2);
    float n0 = sqrtf(s0), n1 = sqrtf(s1);
    float i0 = 1.0f / fmaxf(n0, 1e-12f), i1 = 1.0f / fmaxf(n1, 1e-12f);
    if ((lane & 3) == 0) {
        g_norm[(size_t)b * NN + nb0 + wid * 16 + (lane >> 2)] = n0;
        g_norm[(size_t)b * NN + nb0 + wid * 16 + (lane >> 2) + 8] = n1;
    }

    __syncthreads();  // done reading xs; reuse as hn staging
    {
        const int r = wid * 16 + (lane >> 2);
#pragma unroll
        for (int j = 0; j < 16; j++) {
            *(uint32_t*)(xs + r * 272 + j * 16 + 4 * (lane & 3)) =
                pack_h2(Hf[j * 4 + 0] * i0, Hf[j * 4 + 1] * i0);
            *(uint32_t*)(xs + (r + 8) * 272 + j * 16 + 4 * (lane & 3)) =
                pack_h2(Hf[j * 4 + 2] * i1, Hf[j * 4 + 3] * i1);
        }
    }
    __syncthreads();
    {
        unsigned short* hng = g_hn + ((size_t)b * NN + nb0) * CC;
#pragma unroll
        for (int it = 0; it < 8; it++) {
            int i = tid + it * 256;
            int row = i >> 4, ch = i & 15;
            *(float4*)(hng + (size_t)row * 128 + ch * 8) = *(const float4*)(xs + row * 272 + ch * 16);
        }
    }
}

// =====================================================================
// Kernel 2: S = hn_p.hn_q^T ; O += (edge*S*norm_q).hn_q ; ReLU
// grid (16,8), 256 threads: 8 warps, each m16 x FULL n128 (no split).
// MMA2 B-fragments come from MMA1 B-fragments via movmatrix (no 2nd load).
// =====================================================================
#define EPITCH 132                       // floats per edge row (528B; 4-bank row shift)
#define EBUF (128 * EPITCH * 4)          // 67584 B per parity (full 128 q-cols)
#define OFF_T 0                          // 2 hn tiles (ping-pong)
#define OFF_E (2 * TILE_B)               // 2 edge buffers (parity)
#define OFF_N (OFF_E + 2 * EBUF)         // 2 x 128 norm floats
#define K2_SMEM (OFF_N + 1024)           // 205824 B

// stage one 128x128 fp16 tile (row-major, 256B rows) -> SMEM pitch 272B (256 thr)
__device__ __forceinline__ void stage_tile(const unsigned short* src, char* dst, int tid) {
#pragma unroll
    for (int it = 0; it < 8; it++) {
        int i = tid + it * 256;
        int row = i >> 4, ch = i & 15;
        cp_async16(smem_u32(dst + row * 272 + ch * 16), src + (size_t)row * 128 + ch * 8);
    }
}
// stage 128 x 128 floats of edge (gmem row pitch NN) -> SMEM pitch 528B (256 thr)
__device__ __forceinline__ void stage_edge(const float* src, char* dst, int tid) {
#pragma unroll
    for (int it = 0; it < 16; it++) {
        int i = tid + it * 256;
        int row = i >> 5, ch = i & 31;
        cp_async16(smem_u32(dst + row * 528 + ch * 16), src + (size_t)row * NN + ch * 4);
    }
}

__global__ __launch_bounds__(256, 1) void k2_fused(const float* __restrict__ edge,
                                                   float* __restrict__ out) {
    extern __shared__ char smc[];
    const int b = blockIdx.y, p = blockIdx.x;
    const int tid = threadIdx.x, wid = tid >> 5, lane = tid & 31;

    const unsigned short* hnb = g_hn + (size_t)b * NN * CC;
    const float* eb = edge + ((size_t)b * NN + (size_t)p * 128) * NN;
    const float* nb = g_norm + (size_t)b * NN;

    // ---- preload A1 fragments (hn_p, m16 per warp, persistent) ----
    stage_tile(hnb + (size_t)p * 128 * CC, smc + OFF_T, tid);
    CP_COMMIT(); CP_WAIT0(); __syncthreads();

    uint32_t a1f[32];
    {
        uint32_t ra = smem_u32(smc + OFF_T) + (uint32_t)((wid * 16 + (lane & 15)) * 272)
                    + ((lane & 16) ? 16 : 0);
#pragma unroll
        for (int kk = 0; kk < 8; kk++) ldsm_x4(a1f + 4 * kk, ra + kk * 32);
    }
    __syncthreads();  // A1 in regs; tile buf 0 reusable

    float Of[64];
#pragma unroll
    for (int i = 0; i < 64; i++) Of[i] = 0.0f;

    // pipeline prologue: q=0 -> parity 0 buffers
    stage_tile(hnb, smc + OFF_T, tid);
    stage_edge(eb, smc + OFF_E, tid);
    if (tid < 32) cp_async16(smem_u32(smc + OFF_N) + tid * 16, nb + tid * 4);
    CP_COMMIT();

    const int r0 = wid * 16 + (lane >> 2);   // m-row (within p-tile)
    const int c0 = 2 * (lane & 3);
    const uint32_t b1off = (uint32_t)(((lane & 7) + ((lane & 16) ? 8 : 0)) * 272)
                         + ((lane & 8) ? 16 : 0);

    for (int q = 0; q < NQT; q++) {
        const int par = q & 1;
        CP_WAIT0();
        __syncthreads();

        // prefetch q+1 into opposite-parity buffers (spans whole q compute)
        if (q < NQT - 1) {
            const int qn = q + 1, pn = par ^ 1;
            stage_tile(hnb + (size_t)qn * 128 * CC, smc + OFF_T + pn * TILE_B, tid);
            stage_edge(eb + (size_t)qn * 128, smc + OFF_E + pn * EBUF, tid);
            if (tid < 32)
                cp_async16(smem_u32(smc + OFF_N) + pn * 512 + tid * 16, nb + qn * 128 + tid * 4);
        }
        CP_COMMIT();

        const uint32_t b1base = smem_u32(smc + OFF_T + par * TILE_B) + b1off;
        const float* ebuf = (const float*)(smc + OFF_E + par * EBUF);
        const float* nbuf = (const float*)(smc + OFF_N + par * 512);

#pragma unroll
        for (int tt = 0; tt < 8; tt++) {
            // ---- MMA1: S[m16, n16] over k=128; keep B mats for MMA2 ----
            uint32_t bmat[8][4];
            float S[8];
#pragma unroll
            for (int i = 0; i < 8; i++) S[i] = 0.0f;
            {
                const uint32_t bb1 = b1base + (uint32_t)(tt * 16 * 272);
#pragma unroll
                for (int kk = 0; kk < 8; kk++) {
                    ldsm_x4(bmat[kk], bb1 + kk * 32);
                    mma16816(S + 0, a1f + 4 * kk, bmat[kk][0], bmat[kk][1]);
                    mma16816(S + 4, a1f + 4 * kk, bmat[kk][2], bmat[kk][3]);
                }
            }
            // ---- gate: S *= edge * norm_q ----
#pragma unroll
            for (int jj = 0; jj < 2; jj++) {
                const int c = tt * 16 + jj * 8 + c0;
                float2 nv = *(const float2*)&nbuf[c];
                float2 e0 = *(const float2*)&ebuf[r0 * EPITCH + c];
                float2 e1 = *(const float2*)&ebuf[(r0 + 8) * EPITCH + c];
                S[jj * 4 + 0] *= e0.x * nv.x; S[jj * 4 + 1] *= e0.y * nv.y;
                S[jj * 4 + 2] *= e1.x * nv.x; S[jj * 4 + 3] *= e1.y * nv.y;
            }
            // ---- pack A2 (m16 x k16) ----
            uint32_t A2[4];
            A2[0] = pack_h2(S[0], S[1]);
            A2[1] = pack_h2(S[2], S[3]);
            A2[2] = pack_h2(S[4], S[5]);
            A2[3] = pack_h2(S[6], S[7]);
            // ---- MMA2: O[m16, n128] += A2 . hn_q[k16, n128] ----
            // B fragments = movmatrix of MMA1's mats (no second ldsm)
#pragma unroll
            for (int j2 = 0; j2 < 16; j2++) {
                uint32_t b0 = movm(bmat[j2 >> 1][j2 & 1]);
                uint32_t b1 = movm(bmat[j2 >> 1][2 + (j2 & 1)]);
                mma16816(Of + j2 * 4, A2, b0, b1);
            }
        }
    }

    // ---- epilogue: ReLU + store (no cross-warp reduction needed) ----
    {
        float* ob = out + ((size_t)b * NN + (size_t)p * 128) * CC;
#pragma unroll
        for (int j2 = 0; j2 < 16; j2++) {
            const int c = j2 * 8 + c0;
            float2 v0, v1;
            v0.x = fmaxf(Of[j2 * 4 + 0], 0.0f);
            v0.y = fmaxf(Of[j2 * 4 + 1], 0.0f);
            v1.x = fmaxf(Of[j2 * 4 + 2], 0.0f);
            v1.y = fmaxf(Of[j2 * 4 + 3], 0.0f);
            *(float2*)&ob[(size_t)r0 * CC + c] = v0;
            *(float2*)&ob[(size_t)(r0 + 8) * CC + c] = v1;
        }
    }
}

// ---------------- host launch ----------------
extern "C" void kernel_launch(void* const* d_in, const int* in_sizes, int n_in,
                              void* d_out, int out_size) {
    (void)out_size;
    const float *x = nullptr, *edge = nullptr, *W = nullptr, *bias = nullptr;
    for (int i = 0; i < n_in; i++) {
        int sz = in_sizes[i];
        if (sz == BB * NN * CC) x = (const float*)d_in[i];
        else if (sz == BB * NN * NN) edge = (const float*)d_in[i];
        else if (sz == CC * CC) W = (const float*)d_in[i];
        else if (sz == CC) bias = (const float*)d_in[i];
    }
    if (!x) x = (const float*)d_in[0];
    if (!edge) edge = (const float*)d_in[1];
    if (!W) W = (const float*)d_in[2];
    if (!bias) bias = (const float*)d_in[3];
    float* out = (float*)d_out;

    cudaFuncSetAttribute(k1_linear_norm, cudaFuncAttributeMaxDynamicSharedMemorySize, K1_SMEM);
    cudaFuncSetAttribute(k2_fused, cudaFuncAttributeMaxDynamicSharedMemorySize, K2_SMEM);

    k1_linear_norm<<<dim3(16, 8), 256, K1_SMEM>>>(x, W, bias);
    k2_fused<<<dim3(16, 8), 256, K2_SMEM>>>(edge, out);
}